// round 9
// baseline (speedup 1.0000x reference)
#include <cuda_runtime.h>
#include <cuda_bf16.h>
#include <cstdint>
#include <cstddef>

#define NN 100000
#define DD 128
#define AA 3
#define PP 50000
#define EE 500000
#define EFN 500000

#define ND  ((size_t)NN * DD)
#define AND ((size_t)AA * NN * DD)
#define PD  ((size_t)PP * DD)

// ---------------- scratch (static device globals; no allocation) ----------------
__device__ float  g_xatt_a[AA * NN * DD];
__device__ float  g_xatt_b[AA * NN * DD];
__device__ float  g_agg   [4 * NN * DD];     // slots 0-2: attr agg; slot 3: family agg
__device__ float  g_esf   [AA * PP * DD];
__device__ float  g_projT [AA * 128 * 128];  // proj^T: [o][i]
__device__ float  g_MT    [AA * 128 * 128];  // (inv(proj)+I)^T: [o][i]
// CSR structures for the 7 edge graphs (0-2: attr dst-seg, 3-5: attr src-seg, 6: family)
__device__ int    g_rowptr[7 * (NN + 1)];
__device__ int    g_fill  [7 * NN];
__device__ int    g_eord  [7 * EE];

// m16n8k16 bf16 mma (sm_80+ portable)
__device__ __forceinline__ void mma16(float* c, const uint32_t* a, uint32_t b0, uint32_t b1) {
    asm volatile("mma.sync.aligned.m16n8k16.row.col.f32.bf16.bf16.f32 "
                 "{%0,%1,%2,%3}, {%4,%5,%6,%7}, {%8,%9}, {%0,%1,%2,%3};"
                 : "+f"(c[0]), "+f"(c[1]), "+f"(c[2]), "+f"(c[3])
                 : "r"(a[0]), "r"(a[1]), "r"(a[2]), "r"(a[3]), "r"(b0), "r"(b1));
}
// split (x,y) into packed bf16x2 hi + lo (x low half, y high half)
__device__ __forceinline__ uint32_t packsplit(float x, float y, uint32_t& lopack) {
    float hx = __bfloat162float(__float2bfloat16(x));
    float hy = __bfloat162float(__float2bfloat16(y));
    uint32_t hi;
    asm("cvt.rn.bf16x2.f32 %0, %1, %2;" : "=r"(hi) : "f"(hy), "f"(hx));
    asm("cvt.rn.bf16x2.f32 %0, %1, %2;" : "=r"(lopack) : "f"(y - hy), "f"(x - hx));
    return hi;
}

// ---------------- weight transpose: dst[b][o][i] = src[b][i][o] -----------------
__global__ void transpose_wt(float* __restrict__ dst, const float* __restrict__ src) {
    int b = blockIdx.x;
    const float* s = src + (size_t)b * 16384;
    float* d = dst + (size_t)b * 16384;
    for (int idx = threadIdx.x; idx < 16384; idx += blockDim.x) {
        int o = idx >> 7, i = idx & 127;
        d[idx] = s[(size_t)i * 128 + o];
    }
}

// ---------------- fp64 in-place Gauss-Jordan inverse, all in SMEM ---------------
// S (128x128 doubles, 131072 B dynamic smem) <- inv(proj[a]); writes
// MT[o][i] = inv[i][o] + (i==o). Row pivoting; column unswap at the end.
__global__ __launch_bounds__(1024)
void inv_kernel(const float* __restrict__ proj) {
    extern __shared__ double S[];            // 128*128
    __shared__ double pv[128];
    __shared__ int    pi[128];
    __shared__ int    perm[128];

    int a = blockIdx.x;
    int tid = threadIdx.x;
    int c = tid & 127, r0 = (tid >> 7) << 4; // col owned; base row (16 rows/thread)

    for (int idx = tid; idx < 16384; idx += 1024)
        S[idx] = (double)proj[(size_t)a * 16384 + idx];
    __syncthreads();

    for (int k = 0; k < 128; k++) {
        // pivot search over rows >= k on column k
        if (tid < 128) {
            pv[tid] = (tid >= k) ? fabs(S[tid * 128 + k]) : -1.0;
            pi[tid] = tid;
        }
        __syncthreads();
        for (int s = 64; s > 0; s >>= 1) {
            if (tid < s && pv[tid + s] > pv[tid]) { pv[tid] = pv[tid + s]; pi[tid] = pi[tid + s]; }
            __syncthreads();
        }
        int piv = pi[0];
        if (tid == 0) perm[k] = piv;
        // swap rows k<->piv; stash row k (pre-normalize) into pv
        if (tid < 128) {
            double vk = S[k * 128 + tid];
            if (piv != k) {
                double vp = S[piv * 128 + tid];
                S[piv * 128 + tid] = vk;
                vk = vp;
            }
            pv[tid] = vk;
        }
        __syncthreads();
        double d = pv[k];
        // normalize row k with implicit identity column: rowk[j] = (j==k ? 1 : a_kj)/d
        if (tid < 128) {
            double nv = ((tid == k) ? 1.0 : pv[tid]) / d;
            S[k * 128 + tid] = nv;
            pv[tid] = nv;
        }
        __syncthreads();
        // elimination: thread owns column c, 16 rows r0..r0+15
        double rk = pv[c];
        double f[16];
        #pragma unroll
        for (int m = 0; m < 16; m++) {
            int r = r0 + m;
            f[m] = (r == k) ? 0.0 : S[r * 128 + k];   // broadcast within warp
        }
        __syncthreads();   // all column-k reads done before overwrite
        #pragma unroll
        for (int m = 0; m < 16; m++) {
            int r = r0 + m;
            if (r != k) {
                double v = S[r * 128 + c];
                if (c == k) v = 0.0;                  // implicit identity col update
                S[r * 128 + c] = v - f[m] * rk;
            }
        }
        __syncthreads();
    }
    // undo row pivots as column swaps, reverse order
    for (int k = 127; k >= 0; k--) {
        int p = perm[k];
        if (p != k && tid < 128) {
            double t = S[tid * 128 + k];
            S[tid * 128 + k] = S[tid * 128 + p];
            S[tid * 128 + p] = t;
        }
        __syncthreads();
    }
    // MT[o][i] = inv[i][o] + (i==o)
    for (int idx = tid; idx < 16384; idx += 1024) {
        int o = idx >> 7, i = idx & 127;
        g_MT[(size_t)a * 16384 + idx] = (float)(S[i * 128 + o] + (i == o ? 1.0 : 0.0));
    }
}

// ---------------- CSR build ------------------------------------------------------
__device__ __forceinline__ void graph_ptrs(int g, const int* eia, const int* eif,
                                           const int** gi, const int** si) {
    if (g < 3)      { *gi = eia + (size_t)g * 2 * EE;            *si = eia + (size_t)g * 2 * EE + EE; }
    else if (g < 6) { *gi = eia + (size_t)(g - 3) * 2 * EE + EE; *si = eia + (size_t)(g - 3) * 2 * EE; }
    else            { *gi = eif + EFN;                           *si = eif; }
}

__global__ void hist_k(const int* __restrict__ eia, const int* __restrict__ eif) {
    int g = blockIdx.y;
    const int *gi, *si;
    graph_ptrs(g, eia, eif, &gi, &si);
    int e = blockIdx.x * blockDim.x + threadIdx.x;
    if (e < EE) atomicAdd(g_fill + (size_t)g * NN + si[e], 1);
}

__global__ __launch_bounds__(1024)
void scan_k() {
    int g = blockIdx.x;
    int* cnt = g_fill + (size_t)g * NN;
    int* rp  = g_rowptr + (size_t)g * (NN + 1);
    __shared__ int partial[1024];
    int tid = threadIdx.x;
    const int chunk = (NN + 1023) / 1024;
    int s = tid * chunk, e = s + chunk; if (e > NN) e = NN; if (s > NN) s = NN;
    int sum = 0;
    #pragma unroll 4
    for (int i = s; i < e; i++) sum += cnt[i];
    partial[tid] = sum;
    __syncthreads();
    for (int off = 1; off < 1024; off <<= 1) {
        int v = (tid >= off) ? partial[tid - off] : 0;
        __syncthreads();
        partial[tid] += v;
        __syncthreads();
    }
    int base = (tid == 0) ? 0 : partial[tid - 1];
    for (int i = s; i < e; i++) {
        int c = cnt[i];
        rp[i] = base;
        cnt[i] = base;
        base += c;
    }
    if (tid == 1023) rp[NN] = base;
}

__global__ void fill_k(const int* __restrict__ eia, const int* __restrict__ eif) {
    int g = blockIdx.y;
    const int *gi, *si;
    graph_ptrs(g, eia, eif, &gi, &si);
    int e = blockIdx.x * blockDim.x + threadIdx.x;
    if (e < EE) {
        int pos = atomicAdd(g_fill + (size_t)g * NN + si[e], 1);
        g_eord[(size_t)g * EE + pos] = gi[e];
    }
}

// ---------------- gather-mean ----------------------------------------------------
// graph = gbase + a, except a==3 maps to graph 6 (family) when fam4 set.
__global__ __launch_bounds__(256)
void gather_mean(const float* __restrict__ data, long dataBStr,
                 int gbase, int fam4, float* __restrict__ outp, long outBStr) {
    int a = blockIdx.y;
    int g = (fam4 && a == 3) ? 6 : (gbase + a);
    const float* d = data + (size_t)a * dataBStr;
    float* o = outp + (size_t)a * outBStr;
    const int* rp = g_rowptr + (size_t)g * (NN + 1);
    const int* eo = g_eord + (size_t)g * EE;

    int node = blockIdx.x * 8 + (threadIdx.x >> 5);
    int lane = threadIdx.x & 31;
    if (node >= NN) return;
    int s = rp[node], e = rp[node + 1];
    float4 acc = make_float4(0.f, 0.f, 0.f, 0.f);
    int j = s;
    for (; j + 1 < e; j += 2) {
        int g0 = eo[j], g1 = eo[j + 1];
        float4 v0 = ((const float4*)(d + (size_t)g0 * DD))[lane];
        float4 v1 = ((const float4*)(d + (size_t)g1 * DD))[lane];
        acc.x += v0.x + v1.x; acc.y += v0.y + v1.y;
        acc.z += v0.z + v1.z; acc.w += v0.w + v1.w;
    }
    if (j < e) {
        float4 v = ((const float4*)(d + (size_t)eo[j] * DD))[lane];
        acc.x += v.x; acc.y += v.y; acc.z += v.z; acc.w += v.w;
    }
    float inv = 1.0f / fmaxf((float)(e - s), 1.0f);
    acc.x *= inv; acc.y *= inv; acc.z *= inv; acc.w *= inv;
    ((float4*)(o + (size_t)node * DD))[lane] = acc;
}

// ---------------- bf16 m16n8k16 fused GEMM, double-buffered ----------------------
// Out[row] = act( In1[row] @ W1^T + In2[row] @ W2^T + bias ), rows gathered if GATHER.
// 3-term bf16 split (hh+lh+hl). 2-stage smem pipeline: phase p computes from stage
// p&1 while phase p+2's LDGs are in flight; one barrier per phase. No reg cap.
#define RSTR 20
static constexpr int STAGE_WORDS = 128 * RSTR;                         // per array
static constexpr int GEMM_SMEM = 1024 + 2 * 4 * STAGE_WORDS * 4;       // 82944

template<bool HAS2, bool GATHER, bool RELU, bool HASBIAS>
__global__ __launch_bounds__(512)
void gemm_tc(const float* __restrict__ In1, int in1Stride, long in1BStr,
             const float* __restrict__ W1, int w1Stride, long w1BStr,
             const float* __restrict__ In2, long in2BStr,
             const float* __restrict__ W2, int w2Stride, long w2BStr,
             const float* __restrict__ bias, long biasBStr,
             const int*   __restrict__ ridx,
             float* __restrict__ Out, long outBStr, int nrows) {
    extern __shared__ __align__(16) char smem[];
    int*      sRow  = (int*)smem;               // 128 ints
    float*    sBias = (float*)(smem + 512);     // 128 floats
    uint32_t* sBase = (uint32_t*)(smem + 1024);

    {
        long a = blockIdx.y;
        In1 += a * in1BStr; W1 += a * w1BStr;
        if (HAS2) { In2 += a * in2BStr; W2 += a * w2BStr; }
        if (HASBIAS) bias += a * biasBStr;
        Out += a * outBStr;
    }

    int tid = threadIdx.x, wid = tid >> 5, lane = tid & 31;
    int g = lane >> 2, tg = lane & 3;
    int warpM = wid >> 2, warpN = wid & 3;
    int row0 = blockIdx.x * 128;

    if (tid < 128) {
        int gr = row0 + tid;
        int e = 0;
        if (gr < nrows) e = GATHER ? ridx[gr] : gr;
        sRow[tid] = e;
        if (HASBIAS) sBias[tid] = bias[tid];
    }
    __syncthreads();

    float acc[2][4][4];
    #pragma unroll
    for (int mt = 0; mt < 2; mt++)
        #pragma unroll
        for (int nt = 0; nt < 4; nt++)
            #pragma unroll
            for (int i = 0; i < 4; i++) acc[mt][nt][i] = 0.0f;

    const int np = HAS2 ? 8 : 4;
    int frr = tid >> 2, fsg = (tid & 3) * 2;   // fill: row 0..127, seg pair base

    float4 rA[2], rB[2];

    auto ldg = [&](int p) {
        int op = HAS2 ? (p >> 2) : 0;
        int kc = (p & 3) * 32;
        #pragma unroll
        for (int q = 0; q < 2; q++) {
            int seg = fsg + q;
            const float* asrc;
            if (op == 0) asrc = In1 + (size_t)sRow[frr] * in1Stride + kc + seg * 4;
            else {
                int g2 = row0 + frr; if (g2 >= nrows) g2 = nrows - 1;
                asrc = In2 + (size_t)g2 * 128 + kc + seg * 4;
            }
            rA[q] = *(const float4*)asrc;
            const float* bw = (op == 0) ? W1 : W2;
            int bst = (op == 0) ? w1Stride : w2Stride;
            rB[q] = *(const float4*)(bw + (size_t)frr * bst + kc + seg * 4);
        }
    };
    auto sts = [&](int p) {
        uint32_t* st  = sBase + (p & 1) * (4 * STAGE_WORDS);
        uint32_t* tAh = st;
        uint32_t* tAl = st + STAGE_WORDS;
        uint32_t* tBh = st + 2 * STAGE_WORDS;
        uint32_t* tBl = st + 3 * STAGE_WORDS;
        #pragma unroll
        for (int q = 0; q < 2; q++) {
            int seg = fsg + q;
            int wa = frr * RSTR + seg * 2;
            uint32_t lo0, lo1;
            uint32_t hi0 = packsplit(rA[q].x, rA[q].y, lo0);
            uint32_t hi1 = packsplit(rA[q].z, rA[q].w, lo1);
            tAh[wa] = hi0; tAh[wa + 1] = hi1;
            tAl[wa] = lo0; tAl[wa + 1] = lo1;
            uint32_t wl0, wl1;
            uint32_t wh0 = packsplit(rB[q].x, rB[q].y, wl0);
            uint32_t wh1 = packsplit(rB[q].z, rB[q].w, wl1);
            tBh[wa] = wh0; tBh[wa + 1] = wh1;
            tBl[wa] = wl0; tBl[wa + 1] = wl1;
        }
    };

    // prologue
    ldg(0);
    sts(0);
    if (np > 1) ldg(1);
    __syncthreads();

    for (int p = 0; p < np; p++) {
        if (p + 1 < np) sts(p + 1);          // regs from ldg(p+1)
        if (p + 2 < np) ldg(p + 2);          // overlap DRAM latency with compute
        uint32_t* st  = sBase + (p & 1) * (4 * STAGE_WORDS);
        uint32_t* sAhi = st;
        uint32_t* sAlo = st + STAGE_WORDS;
        uint32_t* sBhi = st + 2 * STAGE_WORDS;
        uint32_t* sBlo = st + 3 * STAGE_WORDS;
        #pragma unroll
        for (int ks = 0; ks < 2; ks++) {
            int wb = ks * 8 + tg;
            uint32_t aH[2][4], aL[2][4];
            #pragma unroll
            for (int mt = 0; mt < 2; mt++) {
                int rb = (warpM * 32 + mt * 16 + g) * RSTR;
                aH[mt][0] = sAhi[rb + wb];
                aH[mt][1] = sAhi[rb + 8 * RSTR + wb];
                aH[mt][2] = sAhi[rb + wb + 4];
                aH[mt][3] = sAhi[rb + 8 * RSTR + wb + 4];
                aL[mt][0] = sAlo[rb + wb];
                aL[mt][1] = sAlo[rb + 8 * RSTR + wb];
                aL[mt][2] = sAlo[rb + wb + 4];
                aL[mt][3] = sAlo[rb + 8 * RSTR + wb + 4];
            }
            #pragma unroll
            for (int nt = 0; nt < 4; nt++) {
                int nb = (warpN * 32 + nt * 8 + g) * RSTR;
                uint32_t bh0 = sBhi[nb + wb], bh1 = sBhi[nb + wb + 4];
                uint32_t bl0 = sBlo[nb + wb], bl1 = sBlo[nb + wb + 4];
                #pragma unroll
                for (int mt = 0; mt < 2; mt++) {
                    mma16(acc[mt][nt], aH[mt], bh0, bh1);
                    mma16(acc[mt][nt], aL[mt], bh0, bh1);
                    mma16(acc[mt][nt], aH[mt], bl0, bl1);
                }
            }
        }
        __syncthreads();
    }

    // ---- epilogue ----
    #pragma unroll
    for (int mt = 0; mt < 2; mt++) {
        #pragma unroll
        for (int half = 0; half < 2; half++) {
            int lr = warpM * 32 + mt * 16 + g + half * 8;
            int grow = row0 + lr;
            if (grow < nrows) {
                int orow = GATHER ? sRow[lr] : grow;
                float* ob = Out + (size_t)orow * 128;
                #pragma unroll
                for (int nt = 0; nt < 4; nt++) {
                    int col = warpN * 32 + nt * 8 + tg * 2;
                    float v0 = acc[mt][nt][half * 2 + 0];
                    float v1 = acc[mt][nt][half * 2 + 1];
                    if (HASBIAS) { v0 += sBias[col]; v1 += sBias[col + 1]; }
                    if (RELU) { v0 = fmaxf(v0, 0.0f); v1 = fmaxf(v1, 0.0f); }
                    float2 pp; pp.x = v0; pp.y = v1;
                    *(float2*)(ob + col) = pp;
                }
            }
        }
    }
}

// ---------------- host orchestration -------------------------------------------
extern "C" void kernel_launch(void* const* d_in, const int* in_sizes, int n_in,
                              void* d_out, int out_size) {
    int iXI, iXA, iPF, iPOP, iEIA, iEIF, iPROJ, iAGGW, iAGGB,
        iWL1, iBL1, iWR1, iWL2, iBL2, iWR2, iWL3, iBL3, iWR3;
    if (in_sizes[3] == PP) {  // setup_inputs dict order
        iXI = 0; iXA = 1; iPF = 2; iPOP = 3; iEIA = 4; iEIF = 5;
        iPROJ = 6; iAGGW = 7; iAGGB = 8; iWL1 = 9; iBL1 = 10; iWR1 = 11;
        iWL2 = 12; iBL2 = 13; iWR2 = 14; iWL3 = 15; iBL3 = 16; iWR3 = 17;
    } else {                  // reference() signature order
        iXI = 0; iXA = 1; iPF = 2; iPROJ = 3; iAGGW = 4; iAGGB = 5;
        iWL1 = 6; iBL1 = 7; iWR1 = 8; iWL2 = 9; iBL2 = 10; iWR2 = 11;
        iWL3 = 12; iBL3 = 13; iWR3 = 14; iPOP = 15; iEIA = 16; iEIF = 17;
    }

    const float* xi   = (const float*)d_in[iXI];
    const float* xa   = (const float*)d_in[iXA];
    const float* pf   = (const float*)d_in[iPF];
    const int*   pop  = (const int*)d_in[iPOP];
    const int*   eia  = (const int*)d_in[iEIA];
    const int*   eif  = (const int*)d_in[iEIF];
    const float* proj = (const float*)d_in[iPROJ];
    const float* aggW = (const float*)d_in[iAGGW];
    const float* aggB = (const float*)d_in[iAGGB];
    const float* wl1  = (const float*)d_in[iWL1];
    const float* bl1  = (const float*)d_in[iBL1];
    const float* wr1  = (const float*)d_in[iWR1];
    const float* wl2  = (const float*)d_in[iWL2];
    const float* bl2  = (const float*)d_in[iBL2];
    const float* wr2  = (const float*)d_in[iWR2];
    const float* wl3  = (const float*)d_in[iWL3];
    const float* bl3  = (const float*)d_in[iBL3];
    const float* wr3  = (const float*)d_in[iWR3];

    float* out = (float*)d_out;  // [x_ind_out (N*D)] then [x_att_out (A*N*D)]

    float *xatt_a, *xatt_b, *agg, *esf, *projT, *MT;
    int *fillp;
    cudaGetSymbolAddress((void**)&xatt_a, g_xatt_a);
    cudaGetSymbolAddress((void**)&xatt_b, g_xatt_b);
    cudaGetSymbolAddress((void**)&agg,    g_agg);
    cudaGetSymbolAddress((void**)&esf,    g_esf);
    cudaGetSymbolAddress((void**)&projT,  g_projT);
    cudaGetSymbolAddress((void**)&MT,     g_MT);
    cudaGetSymbolAddress((void**)&fillp,  g_fill);
    float* agg3 = agg + 3 * ND;

    cudaFuncSetAttribute(inv_kernel, cudaFuncAttributeMaxDynamicSharedMemorySize, 131072);
    cudaFuncSetAttribute(gemm_tc<false, false, false, false>,
                         cudaFuncAttributeMaxDynamicSharedMemorySize, GEMM_SMEM);
    cudaFuncSetAttribute(gemm_tc<true, true, true, true>,
                         cudaFuncAttributeMaxDynamicSharedMemorySize, GEMM_SMEM);
    cudaFuncSetAttribute(gemm_tc<true, false, false, true>,
                         cudaFuncAttributeMaxDynamicSharedMemorySize, GEMM_SMEM);
    cudaFuncSetAttribute(gemm_tc<false, true, true, false>,
                         cudaFuncAttributeMaxDynamicSharedMemorySize, GEMM_SMEM);

    const int gP = (PP + 127) / 128;  // 391
    const int gN = (NN + 127) / 128;  // 782
    const int eB = (EE + 255) / 256;
    const int nB = (NN + 7) / 8;

    // --- prep: transposes + inverse (smem GJ) ---
    transpose_wt<<<AA, 256>>>(projT, proj);
    inv_kernel<<<AA, 1024, 131072>>>(proj);

    // --- CSR build for all 7 graphs ---
    cudaMemsetAsync(fillp, 0, (size_t)7 * NN * sizeof(int), 0);
    hist_k<<<dim3(eB, 7), 256>>>(eia, eif);
    scan_k<<<7, 1024>>>();
    fill_k<<<dim3(eB, 7), 256>>>(eia, eif);

    // 3) esf[a] = PF[:,a,:] @ proj[a]
    gemm_tc<false, false, false, false><<<dim3(gP, AA), 512, GEMM_SMEM>>>(
        pf, AA * DD, DD, projT, 128, 16384,
        nullptr, 0, nullptr, 0, 0, nullptr, 0, nullptr,
        esf, (long)PD, PP);

    // 4) x_att_a = copy(xa); population rows = relu([xa[pop], esf] @ aggW^T + b)
    cudaMemcpyAsync(xatt_a, xa, AND * sizeof(float), cudaMemcpyDeviceToDevice, 0);
    gemm_tc<true, true, true, true><<<dim3(gP, AA), 512, GEMM_SMEM>>>(
        xa, DD, (long)ND, aggW, 256, 0,
        esf, (long)PD, aggW + 128, 256, 0,
        aggB, 0, pop,
        xatt_a, (long)ND, PP);

    // 5+10) agg[a] = seg-mean of xi: graphs 0-2 (dst-seg) and 6 (family) together
    gather_mean<<<dim3(nB, 4), 256>>>(xi, 0, 0, 1, agg, (long)ND);

    // 6) x_att_b = agg @ W_l1^T + b_l1 + x_att_a @ W_r1^T
    gemm_tc<true, false, false, true><<<dim3(gN, AA), 512, GEMM_SMEM>>>(
        agg, DD, (long)ND, wl1, 128, 16384,
        xatt_a, (long)ND, wr1, 128, 16384,
        bl1, DD, nullptr,
        xatt_b, (long)ND, NN);

    // 7) population rows: x_att_b[pop] = relu(x_att_b[pop] @ (inv(proj)+I))
    gemm_tc<false, true, true, false><<<dim3(gP, AA), 512, GEMM_SMEM>>>(
        xatt_b, DD, (long)ND, MT, 128, 16384,
        nullptr, 0, nullptr, 0, 0, nullptr, 0, pop,
        xatt_b, (long)ND, PP);

    // 8) agg[a] = seg-mean of x_att_b over src (graphs 3-5)
    gather_mean<<<dim3(nB, AA), 256>>>(xatt_b, (long)ND, 3, 0, agg, (long)ND);

    // 9) x_att_out = agg @ W_l2^T + b_l2 + x_att_b @ W_r2^T  -> d_out[N*D:]
    gemm_tc<true, false, false, true><<<dim3(gN, AA), 512, GEMM_SMEM>>>(
        agg, DD, (long)ND, wl2, 128, 16384,
        xatt_b, (long)ND, wr2, 128, 16384,
        bl2, DD, nullptr,
        out + ND, (long)ND, NN);

    // 11) x_ind_out = agg3 @ W_l3^T + b_l3 + xi @ W_r3^T -> d_out[0:]
    gemm_tc<true, false, false, true><<<dim3(gN, 1), 512, GEMM_SMEM>>>(
        agg3, DD, 0, wl3, 128, 0,
        xi, 0, wr3, 128, 0,
        bl3, 0, nullptr,
        out, 0, NN);
}